// round 16
// baseline (speedup 1.0000x reference)
#include <cuda_runtime.h>
#include <cuda_fp16.h>
#include <mma.h>
#include <cstdint>
#include <string.h>
#include <math.h>

using namespace nvcuda;

// ===========================================================================
//  xp  = split2(lrelu(x))              [32768,256]  elementwise prep
//  M_n = (WQ_n @ WK_n^T)/sqrt(512)     [8,512,512]  WMMA 3-term
//  E_n = W_enc @ M_n                   [8,256,512]  WMMA 3-term
//  bv_n = b_enc @ M_n                  [8,512]      FFMA GEMV
//  h   = xp @ W_enc^T planes + b       [32768,512]  WMMA 3-term
//  Q'  = xp_a @ E_n^T planes + bv_n    [8,8192,512] WMMA 3-term, K=256
//  attn fused: S=Q'@h^T (3-term) -> softmax -> U=P@h (1-term fp16)
//  out = (1/8) U @ WVcat               [8192,512]   WMMA 1-term fp16
// This round: k_mma CTA tile 128x256, warp tile 64x64 (2x4 warps) ->
// fragment loads per MMA drop 0.5 -> 0.33; 2-stage single-sync cp.async.
// ===========================================================================

// -------------------- scratch (device globals) -----------------------------
static __device__ float  g_M [8u * 512u * 512u];
static __device__ float  g_E [8u * 256u * 512u];
static __device__ float  g_bv[8u * 512u];
static __device__ __half g_x0[32768u * 256u], g_x1[32768u * 256u];
static __device__ __half g_h0[32768u * 512u],  g_h1[32768u * 512u];
static __device__ __half g_Q0[8u * 8192u * 512u], g_Q1[8u * 8192u * 512u];
static __device__ __half g_U0[8192u * 4096u];
static __device__ __half g_Te0[512u * 256u],  g_Te1[512u * 256u];          // W_enc^T
static __device__ __half g_We0[256u * 512u],  g_We1[256u * 512u];          // W_enc (row)
static __device__ __half g_Tm0[8u * 512u * 512u], g_Tm1[8u * 512u * 512u]; // M^T
static __device__ __half g_TE0[8u * 512u * 256u], g_TE1[8u * 512u * 256u]; // E^T
static __device__ __half g_Tw0[512u * 4096u], g_Tw1[512u * 4096u];         // WVcat^T
static __device__ __half g_Wk0[8u * 512u * 512u], g_Wk1[8u * 512u * 512u]; // WK
static __device__ __half g_Wq0[8u * 512u * 512u], g_Wq1[8u * 512u * 512u]; // WQ

__device__ __forceinline__ float lrelu(float v) { return v > 0.0f ? v : 0.01f * v; }

__device__ __forceinline__ void split2(float v, __half& h0, __half& h1) {
    h0 = __float2half_rn(v);
    h1 = __float2half_rn(v - __half2float(h0));
}

__device__ __forceinline__ uint32_t h2u(__half2 v) {
    uint32_t u;
    memcpy(&u, &v, 4);
    return u;
}

// -------------------- cp.async helpers --------------------------------------
__device__ __forceinline__ void cp16(void* sdst, const void* gsrc) {
    uint32_t s = (uint32_t)__cvta_generic_to_shared(sdst);
    asm volatile("cp.async.cg.shared.global [%0], [%1], 16;" :: "r"(s), "l"(gsrc));
}
#define CP_COMMIT() asm volatile("cp.async.commit_group;" ::: "memory")
__device__ __forceinline__ void cp_wait0() { asm volatile("cp.async.wait_group 0;" ::: "memory"); }
__device__ __forceinline__ void cp_wait1() { asm volatile("cp.async.wait_group 1;" ::: "memory"); }

// ---------------------------------------------------------------------------
// xp = split2(lrelu(x)) elementwise, vectorized
// ---------------------------------------------------------------------------
__global__ __launch_bounds__(256) void k_xsplit(const float* __restrict__ X,
                                                __half* __restrict__ T0,
                                                __half* __restrict__ T1,
                                                size_t total4) {
    for (size_t i = (size_t)blockIdx.x * 256 + threadIdx.x; i < total4;
         i += (size_t)gridDim.x * 256) {
        float4 v = ((const float4*)X)[i];
        v.x = lrelu(v.x); v.y = lrelu(v.y); v.z = lrelu(v.z); v.w = lrelu(v.w);
        __align__(8) __half a[4], b[4];
        split2(v.x, a[0], b[0]); split2(v.y, a[1], b[1]);
        split2(v.z, a[2], b[2]); split2(v.w, a[3], b[3]);
        ((uint2*)T0)[i] = *(uint2*)a;
        ((uint2*)T1)[i] = *(uint2*)b;
    }
}

// ---------------------------------------------------------------------------
// three elementwise fp16 split2 jobs fused into one launch
// ---------------------------------------------------------------------------
__global__ __launch_bounds__(256) void k_split3(
    const float* __restrict__ A, __half* __restrict__ A0, __half* __restrict__ A1, size_t na,
    const float* __restrict__ B, __half* __restrict__ B0, __half* __restrict__ B1, size_t nb,
    const float* __restrict__ C, __half* __restrict__ C0, __half* __restrict__ C1, size_t nc) {
    const size_t stride = (size_t)gridDim.x * 256;
    const size_t t0 = (size_t)blockIdx.x * 256 + threadIdx.x;
    for (size_t i = t0; i < na; i += stride) split2(A[i], A0[i], A1[i]);
    for (size_t i = t0; i < nb; i += stride) split2(B[i], B0[i], B1[i]);
    for (size_t i = t0; i < nc; i += stride) split2(C[i], C0[i], C1[i]);
}

// ---------------------------------------------------------------------------
// tiled transpose + fp16 split2:  T*[n*K+k] = split(B[k*N+n])
// ---------------------------------------------------------------------------
__global__ __launch_bounds__(256) void k_tsplit2(const float* __restrict__ B,
                                                 __half* __restrict__ T0,
                                                 __half* __restrict__ T1,
                                                 int K, int N) {
    __shared__ __half s0[32][33];
    __shared__ __half s1[32][33];
    const size_t base = (size_t)blockIdx.z * (size_t)K * N;
    const int k0 = blockIdx.x * 32, n0 = blockIdx.y * 32;
    const int tx = threadIdx.x, ty = threadIdx.y;
#pragma unroll
    for (int i = 0; i < 4; i++) {
        int row = ty * 4 + i;
        float v = B[base + (size_t)(k0 + row) * N + n0 + tx];
        split2(v, s0[row][tx], s1[row][tx]);
    }
    __syncthreads();
#pragma unroll
    for (int i = 0; i < 4; i++) {
        int nrow = ty * 4 + i;
        size_t o = base + (size_t)(n0 + nrow) * K + k0 + tx;
        T0[o] = s0[tx][nrow];
        T1[o] = s1[tx][nrow];
    }
}

// ---------------------------------------------------------------------------
// bv_n = b_enc @ M_n : [8,512]
// ---------------------------------------------------------------------------
__global__ __launch_bounds__(512) void k_bv(const float* __restrict__ b_enc) {
    const int n = blockIdx.x, j = threadIdx.x;
    const float* Mn = g_M + (size_t)n * 512 * 512;
    float s = 0.0f;
    for (int k = 0; k < 512; k++) s += b_enc[k] * Mn[(size_t)k * 512 + j];
    g_bv[n * 512 + j] = s;
}

// ---------------------------------------------------------------------------
// WMMA GEMM, 256 thr, CTA tile 128(M) x 256(N), warp tile 64x64 (2x4 warps),
// K-chunk 64, 2-stage cp.async, single __syncthreads per K-tile.
// Epilogue stages C fp32 through smem: needs >= 128*256*4 = 131072 B.
// ---------------------------------------------------------------------------
template <int NT>
__global__ __launch_bounds__(256) void k_mma(
    const __half* __restrict__ A0g, const __half* __restrict__ A1g,
    const __half* __restrict__ B0g, const __half* __restrict__ B1g,
    float* __restrict__ Cf, __half* __restrict__ C0g, __half* __restrict__ C1g,
    const float* __restrict__ bias, long long biasHi, float alpha,
    int Ktot, int lda, int ldb, int ldc, int gather,
    long long aHi, long long bHi, long long cHi)
{
    constexpr int LDA = 72, LDB = 72;
    constexpr int PL  = (NT > 1) ? 2 : 1;
    constexpr int APL = 128 * LDA * 2;     // 18432 per plane
    constexpr int BPL = 256 * LDB * 2;     // 36864 per plane
    constexpr int STAGE = PL * (APL + BPL);

    extern __shared__ __align__(1024) char sm[];

    const int tid = threadIdx.x;
    const int w = tid >> 5;
    const int wm = w & 1;      // 2 groups of 64 rows
    const int wn = w >> 1;     // 4 groups of 64 cols
    const long long aoff = (long long)blockIdx.z * aHi;
    const long long boff = (long long)blockIdx.z * bHi;
    const long long coff = (long long)blockIdx.z * cHi;
    const float* biasz = bias ? (bias + (long long)blockIdx.z * biasHi) : (const float*)0;
    const int m0 = blockIdx.y * 128;
    const int n0 = blockIdx.x * 256;

    // A: 128 rows x 8 chunks = 1024 cps/plane -> 4/thread
    // B: 256 rows x 8 chunks = 2048 cps/plane -> 8/thread
    int arw[4], ak[4], brw[8], bk[8];
#pragma unroll
    for (int i = 0; i < 4; i++) {
        int id = tid + i * 256;
        arw[i] = id >> 3;
        ak[i] = (id & 7) * 8;
    }
#pragma unroll
    for (int i = 0; i < 8; i++) {
        int id = tid + i * 256;
        brw[i] = id >> 3;
        bk[i] = (id & 7) * 8;
    }

    auto a_row = [&](int r) -> long long {
        int g = m0 + r;
        return gather ? (long long)(((g >> 6) << 8) + (g & 63)) : (long long)g;
    };

    wmma::fragment<wmma::accumulator, 16, 16, 16, float> acc[4][4];
#pragma unroll
    for (int mf = 0; mf < 4; mf++)
#pragma unroll
        for (int nf = 0; nf < 4; nf++) wmma::fill_fragment(acc[mf][nf], 0.0f);

    auto cp_tile = [&](int k0, int buf) {
        char* base = sm + buf * STAGE;
        __half* sA0 = (__half*)base;
        __half* sA1 = (__half*)(base + APL);
        __half* sB0 = (__half*)(base + PL * APL);
        __half* sB1 = (__half*)(base + PL * APL + BPL);
#pragma unroll
        for (int i = 0; i < 4; i++) {
            long long ga = aoff + a_row(arw[i]) * lda + k0 + ak[i];
            cp16(sA0 + arw[i] * LDA + ak[i], A0g + ga);
            if (NT > 1) cp16(sA1 + arw[i] * LDA + ak[i], A1g + ga);
        }
#pragma unroll
        for (int i = 0; i < 8; i++) {
            long long gb = boff + (long long)(n0 + brw[i]) * ldb + k0 + bk[i];
            cp16(sB0 + brw[i] * LDB + bk[i], B0g + gb);
            if (NT > 1) cp16(sB1 + brw[i] * LDB + bk[i], B1g + gb);
        }
        CP_COMMIT();
    };

    auto mma_tile = [&](int buf) {
        const char* base = sm + buf * STAGE;
        const __half* sA0 = (const __half*)(base);
        const __half* sA1 = (const __half*)(base + APL);
        const __half* sB0 = (const __half*)(base + PL * APL);
        const __half* sB1 = (const __half*)(base + PL * APL + BPL);
#pragma unroll
        for (int ks = 0; ks < 64; ks += 16) {
            wmma::fragment<wmma::matrix_a, 16, 16, 16, __half, wmma::row_major> a0f[4], a1f[4];
#pragma unroll
            for (int mf = 0; mf < 4; mf++) {
                int r0 = wm * 64 + mf * 16;
                wmma::load_matrix_sync(a0f[mf], sA0 + r0 * LDA + ks, LDA);
                if (NT > 1) wmma::load_matrix_sync(a1f[mf], sA1 + r0 * LDA + ks, LDA);
            }
#pragma unroll
            for (int nf = 0; nf < 4; nf++) {
                int col = wn * 64 + nf * 16;
                wmma::fragment<wmma::matrix_b, 16, 16, 16, __half, wmma::col_major> b0f, b1f;
                wmma::load_matrix_sync(b0f, sB0 + col * LDB + ks, LDB);
                if (NT > 1) wmma::load_matrix_sync(b1f, sB1 + col * LDB + ks, LDB);
#pragma unroll
                for (int mf = 0; mf < 4; mf++) {
                    wmma::mma_sync(acc[mf][nf], a0f[mf], b0f, acc[mf][nf]);
                    if (NT > 1) {
                        wmma::mma_sync(acc[mf][nf], a0f[mf], b1f, acc[mf][nf]);
                        wmma::mma_sync(acc[mf][nf], a1f[mf], b0f, acc[mf][nf]);
                    }
                }
            }
        }
    };

    const int numK = Ktot >> 6;
    cp_tile(0, 0);
    for (int t = 0; t < numK; t++) {
        cp_wait0();
        __syncthreads();
        if (t + 1 < numK) cp_tile((t + 1) << 6, (t + 1) & 1);
        mma_tile(t & 1);
    }
    __syncthreads();

    float* Csm = (float*)sm;
#pragma unroll
    for (int mf = 0; mf < 4; mf++)
#pragma unroll
        for (int nf = 0; nf < 4; nf++) {
            int r0 = wm * 64 + mf * 16, c0 = wn * 64 + nf * 16;
            wmma::store_matrix_sync(Csm + r0 * 256 + c0, acc[mf][nf], 256, wmma::mem_row_major);
        }
    __syncthreads();

    // 128 rows x 256 cols fp32 -> 32 float4 per thread
#pragma unroll
    for (int i = 0; i < 32; i++) {
        int f = tid + i * 256;
        int row = f >> 6, c4 = (f & 63) * 4;
        float4 v = *(float4*)(Csm + row * 256 + c4);
        v.x *= alpha; v.y *= alpha; v.z *= alpha; v.w *= alpha;
        if (biasz) {
            v.x += biasz[n0 + c4 + 0]; v.y += biasz[n0 + c4 + 1];
            v.z += biasz[n0 + c4 + 2]; v.w += biasz[n0 + c4 + 3];
        }
        long long o = coff + (long long)(m0 + row) * ldc + n0 + c4;
        if (Cf) {
            *(float4*)(Cf + o) = v;
        } else {
            __half x0, x1, y0, y1, z0, z1, w0, w1;
            split2(v.x, x0, x1); split2(v.y, y0, y1);
            split2(v.z, z0, z1); split2(v.w, w0, w1);
            __half2 p0 = __halves2half2(x0, y0), q0 = __halves2half2(z0, w0);
            *(uint2*)(C0g + o) = make_uint2(h2u(p0), h2u(q0));
            if (C1g) {
                __half2 p1 = __halves2half2(x1, y1), q1 = __halves2half2(z1, w1);
                *(uint2*)(C1g + o) = make_uint2(h2u(p1), h2u(q1));
            }
        }
    }
}

// ---------------------------------------------------------------------------
// Fused attention per (b, n) CTA.  (unchanged from round 15)
// Phase1: K=64, 2-stage cp.async, single sync per K-tile (8 tiles).
// Phase3: 3-stage 16896 each.
// ---------------------------------------------------------------------------
#define ATTN_SMEM 184320
#define P1_STAGE 92160
#define P1_APL 9216
#define P1_BOFF 18432
#define P1_BPL 36864

__global__ __launch_bounds__(256) void k_attn() {
    extern __shared__ __align__(1024) char sm[];
    const int tid = threadIdx.x;
    const int w = tid >> 5, lane = tid & 31;
    const int wm = w & 1, wn = w >> 1;
    const int b = blockIdx.x, n = blockIdx.y;

    float* Ssm = (float*)sm;
    __half* Psm0 = (__half*)(sm + 67584);

    const __half* Qb0 = g_Q0 + ((size_t)n * 8192 + (size_t)b * 64) * 512;
    const __half* Qb1 = g_Q1 + ((size_t)n * 8192 + (size_t)b * 64) * 512;
    const __half* Hb0 = g_h0 + (size_t)b * 256 * 512;
    const __half* Hb1 = g_h1 + (size_t)b * 256 * 512;

    wmma::fragment<wmma::accumulator, 16, 16, 16, float> acc[2][4];
#pragma unroll
    for (int mf = 0; mf < 2; mf++)
#pragma unroll
        for (int nf = 0; nf < 4; nf++) wmma::fill_fragment(acc[mf][nf], 0.0f);

    // ======== phase 1: S = Q' @ h^T  (K=512, 8 chunks of 64, 3-term) ======
    {
        auto p1_cp = [&](int k0, int buf) {
            char* base = sm + buf * P1_STAGE;
            __half* sA0 = (__half*)base;
            __half* sA1 = (__half*)(base + P1_APL);
            __half* sB0 = (__half*)(base + P1_BOFF);
            __half* sB1 = (__half*)(base + P1_BOFF + P1_BPL);
#pragma unroll
            for (int i = 0; i < 2; i++) {
                int id = tid + i * 256;
                int ar = id >> 3, akc = (id & 7) * 8;
                long long ga = (size_t)ar * 512 + k0 + akc;
                cp16(sA0 + ar * 72 + akc, Qb0 + ga);
                cp16(sA1 + ar * 72 + akc, Qb1 + ga);
            }
#pragma unroll
            for (int i = 0; i < 8; i++) {
                int id = tid + i * 256;
                int br = id >> 3, bkc = (id & 7) * 8;
                long long gb = (size_t)br * 512 + k0 + bkc;
                cp16(sB0 + br * 72 + bkc, Hb0 + gb);
                cp16(sB1 + br * 72 + bkc, Hb1 + gb);
            }
            CP_COMMIT();
        };
        auto p1_mma = [&](int buf) {
            const char* base = sm + buf * P1_STAGE;
            const __half* sA0 = (const __half*)base;
            const __half* sA1 = (const __half*)(base + P1_APL);
            const __half* sB0 = (const __half*)(base + P1_BOFF);
            const __half* sB1 = (const __half*)(base + P1_BOFF + P1_BPL);
#pragma unroll
            for (int ks = 0; ks < 64; ks += 16) {
                wmma::fragment<wmma::matrix_a, 16, 16, 16, __half, wmma::row_major> a0f[2], a1f[2];
#pragma unroll
                for (int mf = 0; mf < 2; mf++) {
                    int r0 = wm * 32 + mf * 16;
                    wmma::load_matrix_sync(a0f[mf], sA0 + r0 * 72 + ks, 72);
                    wmma::load_matrix_sync(a1f[mf], sA1 + r0 * 72 + ks, 72);
                }
#pragma unroll
                for (int nf = 0; nf < 4; nf++) {
                    int col = wn * 64 + nf * 16;
                    wmma::fragment<wmma::matrix_b, 16, 16, 16, __half, wmma::col_major> b0f, b1f;
                    wmma::load_matrix_sync(b0f, sB0 + col * 72 + ks, 72);
                    wmma::load_matrix_sync(b1f, sB1 + col * 72 + ks, 72);
#pragma unroll
                    for (int mf = 0; mf < 2; mf++) {
                        wmma::mma_sync(acc[mf][nf], a0f[mf], b0f, acc[mf][nf]);
                        wmma::mma_sync(acc[mf][nf], a0f[mf], b1f, acc[mf][nf]);
                        wmma::mma_sync(acc[mf][nf], a1f[mf], b0f, acc[mf][nf]);
                    }
                }
            }
        };
        p1_cp(0, 0);
        for (int t = 0; t < 8; t++) {
            cp_wait0();
            __syncthreads();
            if (t + 1 < 8) p1_cp((t + 1) << 6, (t + 1) & 1);
            p1_mma(t & 1);
        }
        __syncthreads();
    }

    // ======== stage S -> smem fp32 ========
#pragma unroll
    for (int mf = 0; mf < 2; mf++)
#pragma unroll
        for (int nf = 0; nf < 4; nf++) {
            int r0 = wm * 32 + mf * 16, c0 = wn * 64 + nf * 16;
            wmma::store_matrix_sync(Ssm + r0 * 264 + c0, acc[mf][nf], 264, wmma::mem_row_major);
        }
    __syncthreads();

    // ======== softmax ========
#pragma unroll
    for (int i = 0; i < 8; i++) {
        int r = w * 8 + i;
        float* srow = Ssm + (size_t)r * 264 + lane * 8;
        float4 v0 = *(float4*)srow;
        float4 v1 = *(float4*)(srow + 4);
        float m = fmaxf(fmaxf(fmaxf(v0.x, v0.y), fmaxf(v0.z, v0.w)),
                        fmaxf(fmaxf(v1.x, v1.y), fmaxf(v1.z, v1.w)));
#pragma unroll
        for (int off = 16; off > 0; off >>= 1)
            m = fmaxf(m, __shfl_xor_sync(0xffffffffu, m, off));
        v0.x = __expf(v0.x - m); v0.y = __expf(v0.y - m);
        v0.z = __expf(v0.z - m); v0.w = __expf(v0.w - m);
        v1.x = __expf(v1.x - m); v1.y = __expf(v1.y - m);
        v1.z = __expf(v1.z - m); v1.w = __expf(v1.w - m);
        float s = v0.x + v0.y + v0.z + v0.w + v1.x + v1.y + v1.z + v1.w;
#pragma unroll
        for (int off = 16; off > 0; off >>= 1)
            s += __shfl_xor_sync(0xffffffffu, s, off);
        const float inv = 1.0f / s;
        __align__(16) __half h0[8];
        h0[0] = __float2half_rn(v0.x * inv); h0[1] = __float2half_rn(v0.y * inv);
        h0[2] = __float2half_rn(v0.z * inv); h0[3] = __float2half_rn(v0.w * inv);
        h0[4] = __float2half_rn(v1.x * inv); h0[5] = __float2half_rn(v1.y * inv);
        h0[6] = __float2half_rn(v1.z * inv); h0[7] = __float2half_rn(v1.w * inv);
        *(uint4*)(Psm0 + (size_t)r * 264 + lane * 8) = *(uint4*)h0;
    }
    __syncthreads();

    // ======== phase 3: U = P @ h  (1-term; two halves; K=256; 3-stage) ====
    for (int hh = 0; hh < 2; hh++) {
        const int d0 = hh * 256;
#pragma unroll
        for (int mf = 0; mf < 2; mf++)
#pragma unroll
            for (int nf = 0; nf < 4; nf++) wmma::fill_fragment(acc[mf][nf], 0.0f);

        auto p3_cp = [&](int k0, int buf) {
            __half* sH0 = (__half*)(sm + buf * 16896);
#pragma unroll
            for (int i = 0; i < 4; i++) {
                int id = tid + i * 256;
                int er = id >> 5, dc = (id & 31) * 8;
                cp16(sH0 + er * 264 + dc, Hb0 + (size_t)(k0 + er) * 512 + d0 + dc);
            }
            CP_COMMIT();
        };
        auto p3_mma = [&](int buf, int c) {
            const __half* sH0 = (const __half*)(sm + buf * 16896);
#pragma unroll
            for (int ks = 0; ks < 32; ks += 16) {
                wmma::fragment<wmma::matrix_a, 16, 16, 16, __half, wmma::row_major> a0f[2];
#pragma unroll
                for (int mf = 0; mf < 2; mf++) {
                    int r0 = wm * 32 + mf * 16;
                    wmma::load_matrix_sync(a0f[mf], Psm0 + r0 * 264 + c * 32 + ks, 264);
                }
#pragma unroll
                for (int nf = 0; nf < 4; nf++) {
                    int col = wn * 64 + nf * 16;
                    wmma::fragment<wmma::matrix_b, 16, 16, 16, __half, wmma::row_major> b0f;
                    wmma::load_matrix_sync(b0f, sH0 + ks * 264 + col, 264);
#pragma unroll
                    for (int mf = 0; mf < 2; mf++)
                        wmma::mma_sync(acc[mf][nf], a0f[mf], b0f, acc[mf][nf]);
                }
            }
        };
        p3_cp(0, 0);
        p3_cp(32, 1);
        for (int c = 0; c < 8; c++) {
            if (c + 1 < 8) cp_wait1(); else cp_wait0();
            __syncthreads();
            if (c + 2 < 8) p3_cp((c + 2) << 5, (c + 2) % 3);
            p3_mma(c % 3, c);
        }
        __syncthreads();

        float* Csm = (float*)sm;
#pragma unroll
        for (int mf = 0; mf < 2; mf++)
#pragma unroll
            for (int nf = 0; nf < 4; nf++) {
                int r0 = wm * 32 + mf * 16, c0 = wn * 64 + nf * 16;
                wmma::store_matrix_sync(Csm + r0 * 264 + c0, acc[mf][nf], 264, wmma::mem_row_major);
            }
        __syncthreads();
#pragma unroll
        for (int i = 0; i < 16; i++) {
            int id = tid + i * 256;
            int row = id >> 6, c4 = (id & 63) * 4;
            float4 v = *(float4*)(Csm + row * 264 + c4);
            __align__(8) __half h4[4];
            h4[0] = __float2half_rn(v.x); h4[1] = __float2half_rn(v.y);
            h4[2] = __float2half_rn(v.z); h4[3] = __float2half_rn(v.w);
            size_t o = (((size_t)(b * 64 + row)) * 8 + n) * 512 + d0 + c4;
            *(uint2*)(g_U0 + o) = *(uint2*)h4;
        }
        __syncthreads();
    }
}

// ---------------------------------------------------------------------------
extern "C" void kernel_launch(void* const* d_in, const int* in_sizes, int n_in,
                              void* d_out, int out_size) {
    const float* x     = (const float*)d_in[0];
    const float* W_enc = (const float*)d_in[1];
    const float* b_enc = (const float*)d_in[2];
    const float* WQ    = (const float*)d_in[3];
    const float* WK    = (const float*)d_in[4];
    const float* WV    = (const float*)d_in[5];
    float* out = (float*)d_out;

    // NT3: 2 stages x 110592 = 221184 (also >= epilogue 131072)
    // NT1: max(2 x 55296, 131072) = 131072
    const int SM3 = 221184;
    const int SM1 = 131072;
    cudaFuncSetAttribute(k_mma<3>, cudaFuncAttributeMaxDynamicSharedMemorySize, SM3);
    cudaFuncSetAttribute(k_mma<1>, cudaFuncAttributeMaxDynamicSharedMemorySize, SM1);
    cudaFuncSetAttribute(k_attn, cudaFuncAttributeMaxDynamicSharedMemorySize, ATTN_SMEM);

    void *p_M, *p_E, *p_bv, *p_x0, *p_x1, *p_h0, *p_h1, *p_Q0, *p_Q1, *p_U0;
    void *p_e0, *p_e1, *p_we0, *p_we1, *p_m0, *p_m1, *p_E0, *p_E1;
    void *p_w0, *p_w1, *p_k0, *p_k1, *p_q0, *p_q1;
    cudaGetSymbolAddress(&p_M, g_M);
    cudaGetSymbolAddress(&p_E, g_E);
    cudaGetSymbolAddress(&p_bv, g_bv);
    cudaGetSymbolAddress(&p_x0, g_x0); cudaGetSymbolAddress(&p_x1, g_x1);
    cudaGetSymbolAddress(&p_h0, g_h0); cudaGetSymbolAddress(&p_h1, g_h1);
    cudaGetSymbolAddress(&p_Q0, g_Q0); cudaGetSymbolAddress(&p_Q1, g_Q1);
    cudaGetSymbolAddress(&p_U0, g_U0);
    cudaGetSymbolAddress(&p_e0, g_Te0); cudaGetSymbolAddress(&p_e1, g_Te1);
    cudaGetSymbolAddress(&p_we0, g_We0); cudaGetSymbolAddress(&p_we1, g_We1);
    cudaGetSymbolAddress(&p_m0, g_Tm0); cudaGetSymbolAddress(&p_m1, g_Tm1);
    cudaGetSymbolAddress(&p_E0, g_TE0); cudaGetSymbolAddress(&p_E1, g_TE1);
    cudaGetSymbolAddress(&p_w0, g_Tw0); cudaGetSymbolAddress(&p_w1, g_Tw1);
    cudaGetSymbolAddress(&p_k0, g_Wk0); cudaGetSymbolAddress(&p_k1, g_Wk1);
    cudaGetSymbolAddress(&p_q0, g_Wq0); cudaGetSymbolAddress(&p_q1, g_Wq1);

    // 0: x split
    k_xsplit<<<dim3(2048), 256>>>(x, (__half*)p_x0, (__half*)p_x1, (size_t)32768 * 256 / 4);
    // 1: We + WK + WQ elementwise splits (fused)
    k_split3<<<dim3(512), 256>>>(
        W_enc, (__half*)p_we0, (__half*)p_we1, (size_t)256 * 512,
        WK, (__half*)p_k0, (__half*)p_k1, (size_t)8 * 512 * 512,
        WQ, (__half*)p_q0, (__half*)p_q1, (size_t)8 * 512 * 512);
    // 2: W_enc^T split
    k_tsplit2<<<dim3(8, 16, 1), dim3(32, 8)>>>(W_enc, (__half*)p_e0, (__half*)p_e1, 256, 512);
    // 3: encode (PROFILE TARGET): h planes = xp @ Te + b
    k_mma<3><<<dim3(2, 256, 1), 256, SM3>>>(
        (const __half*)p_x0, (const __half*)p_x1,
        (const __half*)p_e0, (const __half*)p_e1,
        nullptr, (__half*)p_h0, (__half*)p_h1, b_enc, 0, 1.0f,
        256, 256, 256, 512, 0, 0, 0, 0);
    // 4: WV^T split
    k_tsplit2<<<dim3(128, 16, 1), dim3(32, 8)>>>(WV, (__half*)p_w0, (__half*)p_w1, 4096, 512);
    // 5: M_n = (WQ_n @ WK_n^T) * scale
    k_mma<3><<<dim3(2, 4, 8), 256, SM3>>>(
        (const __half*)p_q0, (const __half*)p_q1,
        (const __half*)p_k0, (const __half*)p_k1,
        (float*)p_M, nullptr, nullptr, nullptr, 0, 0.04419417382415922f,
        512, 512, 512, 512, 0,
        (long long)512 * 512, (long long)512 * 512, (long long)512 * 512);
    // 6: M^T split
    k_tsplit2<<<dim3(16, 16, 8), dim3(32, 8)>>>((const float*)p_M, (__half*)p_m0, (__half*)p_m1, 512, 512);
    // 7: bv = b @ M
    k_bv<<<dim3(8), 512>>>(b_enc);
    // 8: E_n = W_enc @ M_n
    k_mma<3><<<dim3(2, 2, 8), 256, SM3>>>(
        (const __half*)p_we0, (const __half*)p_we1,
        (const __half*)p_m0, (const __half*)p_m1,
        (float*)p_E, nullptr, nullptr, nullptr, 0, 1.0f,
        512, 512, 512, 512, 0,
        0, (long long)512 * 512, (long long)256 * 512);
    // 9: E^T split
    k_tsplit2<<<dim3(8, 16, 8), dim3(32, 8)>>>((const float*)p_E, (__half*)p_E0, (__half*)p_E1, 256, 512);
    // 10: Q' = xp_a @ TE + bv  (K=256, gather, batched)
    k_mma<3><<<dim3(2, 64, 8), 256, SM3>>>(
        (const __half*)p_x0, (const __half*)p_x1,
        (const __half*)p_E0, (const __half*)p_E1,
        nullptr, (__half*)p_Q0, (__half*)p_Q1, (const float*)p_bv, 512, 1.0f,
        256, 256, 256, 512, 1,
        0, (long long)512 * 256, (long long)8192 * 512);
    // 11: fused attention
    k_attn<<<dim3(128, 8), 256, ATTN_SMEM>>>();
    // 12: out = (1/8) U @ WVcat  (1-term)
    k_mma<1><<<dim3(2, 64, 1), 256, SM1>>>(
        (const __half*)p_U0, nullptr,
        (const __half*)p_w0, nullptr,
        out, nullptr, nullptr, nullptr, 0, 0.125f,
        4096, 4096, 4096, 512, 0, 0, 0, 0);
}

// round 17
// speedup vs baseline: 1.1228x; 1.1228x over previous
#include <cuda_runtime.h>
#include <cuda_fp16.h>
#include <mma.h>
#include <cstdint>
#include <string.h>
#include <math.h>

using namespace nvcuda;

// ===========================================================================
//  xp  = split2(lrelu(x))            [32768,256]
//  M_n = (WQ_n @ WK_n^T)/sqrt(512)   [8,512,512]  WMMA 3-term
//  E_n = W_enc @ M_n                 [8,256,512]  WMMA 3-term
//  F_n = E_n @ W_enc^T               [8,256,256]  WMMA 3-term (tiny)
//  bv_n = b_enc @ M_n ; w_n = W_enc @ bv_n ; cn_n = bv_n.b_enc
//  s[n,r] = w_n . x~_r + cn_n        (fp32 GEMV; per-column softmax term)
//  h   = xp @ W_enc^T (+b)           [32768,512]  WMMA 3-term, fp16 1-plane out
//  attn fused per (b,n): T = x~a@F_n (3t) -> S = T@x~^T (3t) + s -> softmax
//                        -> U = P@h (1-term fp16)
//  out = (1/8) U @ WVcat             [8192,512]   WMMA 1-term
// Softmax row-invariance drops Q'@b and bv@b terms; qprime GEMM eliminated.
// ===========================================================================

// -------------------- scratch (device globals) -----------------------------
static __device__ float  g_M [8u * 512u * 512u];
static __device__ float  g_E [8u * 256u * 512u];
static __device__ float  g_F [8u * 256u * 256u];
static __device__ float  g_bv[8u * 512u];
static __device__ float  g_w [8u * 256u];
static __device__ float  g_cn[8u];
static __device__ float  g_s [8u * 32768u];
static __device__ __half g_x0[32768u * 256u], g_x1[32768u * 256u];
static __device__ __half g_h0[32768u * 512u];
static __device__ __half g_U0[8192u * 4096u];
static __device__ __half g_Te0[512u * 256u],  g_Te1[512u * 256u];          // W_enc^T
static __device__ __half g_We0[256u * 512u],  g_We1[256u * 512u];          // W_enc row
static __device__ __half g_Tm0[8u * 512u * 512u], g_Tm1[8u * 512u * 512u]; // M^T
static __device__ __half g_TE0[8u * 256u * 512u], g_TE1[8u * 256u * 512u]; // E row
static __device__ __half g_TF0[8u * 256u * 256u], g_TF1[8u * 256u * 256u]; // F^T
static __device__ __half g_Tw0[512u * 4096u], g_Tw1[512u * 4096u];         // WVcat^T
static __device__ __half g_Wk0[8u * 512u * 512u], g_Wk1[8u * 512u * 512u]; // WK
static __device__ __half g_Wq0[8u * 512u * 512u], g_Wq1[8u * 512u * 512u]; // WQ

__device__ __forceinline__ float lrelu(float v) { return v > 0.0f ? v : 0.01f * v; }

__device__ __forceinline__ void split2(float v, __half& h0, __half& h1) {
    h0 = __float2half_rn(v);
    h1 = __float2half_rn(v - __half2float(h0));
}

__device__ __forceinline__ uint32_t h2u(__half2 v) {
    uint32_t u;
    memcpy(&u, &v, 4);
    return u;
}

// -------------------- cp.async helpers --------------------------------------
__device__ __forceinline__ void cp16(void* sdst, const void* gsrc) {
    uint32_t s = (uint32_t)__cvta_generic_to_shared(sdst);
    asm volatile("cp.async.cg.shared.global [%0], [%1], 16;" :: "r"(s), "l"(gsrc));
}
#define CP_COMMIT() asm volatile("cp.async.commit_group;" ::: "memory")
__device__ __forceinline__ void cp_wait0() { asm volatile("cp.async.wait_group 0;" ::: "memory"); }
__device__ __forceinline__ void cp_wait1() { asm volatile("cp.async.wait_group 1;" ::: "memory"); }

// ---------------------------------------------------------------------------
__global__ __launch_bounds__(256) void k_xsplit(const float* __restrict__ X,
                                                __half* __restrict__ T0,
                                                __half* __restrict__ T1,
                                                size_t total4) {
    for (size_t i = (size_t)blockIdx.x * 256 + threadIdx.x; i < total4;
         i += (size_t)gridDim.x * 256) {
        float4 v = ((const float4*)X)[i];
        v.x = lrelu(v.x); v.y = lrelu(v.y); v.z = lrelu(v.z); v.w = lrelu(v.w);
        __align__(8) __half a[4], b[4];
        split2(v.x, a[0], b[0]); split2(v.y, a[1], b[1]);
        split2(v.z, a[2], b[2]); split2(v.w, a[3], b[3]);
        ((uint2*)T0)[i] = *(uint2*)a;
        ((uint2*)T1)[i] = *(uint2*)b;
    }
}

__global__ __launch_bounds__(256) void k_split2e(const float* __restrict__ B,
                                                 __half* __restrict__ T0,
                                                 __half* __restrict__ T1,
                                                 size_t total) {
    for (size_t i = (size_t)blockIdx.x * 256 + threadIdx.x; i < total;
         i += (size_t)gridDim.x * 256) {
        split2(B[i], T0[i], T1[i]);
    }
}

__global__ __launch_bounds__(256) void k_split3(
    const float* __restrict__ A, __half* __restrict__ A0, __half* __restrict__ A1, size_t na,
    const float* __restrict__ B, __half* __restrict__ B0, __half* __restrict__ B1, size_t nb,
    const float* __restrict__ C, __half* __restrict__ C0, __half* __restrict__ C1, size_t nc) {
    const size_t stride = (size_t)gridDim.x * 256;
    const size_t t0 = (size_t)blockIdx.x * 256 + threadIdx.x;
    for (size_t i = t0; i < na; i += stride) split2(A[i], A0[i], A1[i]);
    for (size_t i = t0; i < nb; i += stride) split2(B[i], B0[i], B1[i]);
    for (size_t i = t0; i < nc; i += stride) split2(C[i], C0[i], C1[i]);
}

// tiled transpose + split2:  T*[n*K+k] = split(B[k*N+n])
__global__ __launch_bounds__(256) void k_tsplit2(const float* __restrict__ B,
                                                 __half* __restrict__ T0,
                                                 __half* __restrict__ T1,
                                                 int K, int N) {
    __shared__ __half s0[32][33];
    __shared__ __half s1[32][33];
    const size_t base = (size_t)blockIdx.z * (size_t)K * N;
    const int k0 = blockIdx.x * 32, n0 = blockIdx.y * 32;
    const int tx = threadIdx.x, ty = threadIdx.y;
#pragma unroll
    for (int i = 0; i < 4; i++) {
        int row = ty * 4 + i;
        float v = B[base + (size_t)(k0 + row) * N + n0 + tx];
        split2(v, s0[row][tx], s1[row][tx]);
    }
    __syncthreads();
#pragma unroll
    for (int i = 0; i < 4; i++) {
        int nrow = ty * 4 + i;
        size_t o = base + (size_t)(n0 + nrow) * K + k0 + tx;
        T0[o] = s0[tx][nrow];
        T1[o] = s1[tx][nrow];
    }
}

// bv_n = b_enc @ M_n
__global__ __launch_bounds__(512) void k_bv(const float* __restrict__ b_enc) {
    const int n = blockIdx.x, j = threadIdx.x;
    const float* Mn = g_M + (size_t)n * 512 * 512;
    float s = 0.0f;
    for (int k = 0; k < 512; k++) s += b_enc[k] * Mn[(size_t)k * 512 + j];
    g_bv[n * 512 + j] = s;
}

// w_n = W_enc @ bv_n ; cn_n = bv_n . b_enc
__global__ __launch_bounds__(256) void k_wv(const float* __restrict__ We,
                                            const float* __restrict__ b_enc) {
    const int n = blockIdx.x, i = threadIdx.x;
    const float* bvn = g_bv + n * 512;
    float s = 0.0f;
    for (int d = 0; d < 512; d++) s += We[(size_t)i * 512 + d] * bvn[d];
    g_w[n * 256 + i] = s;
    if (i == 0) {
        float c = 0.0f;
        for (int d = 0; d < 512; d++) c += bvn[d] * b_enc[d];
        g_cn[n] = c;
    }
}

// s[n,r] = w_n . x~_r + cn_n   (warp per row; 8 rows per block)
__global__ __launch_bounds__(256) void k_sv() {
    __shared__ float ws[8 * 256];
    const int tid = threadIdx.x;
    for (int i = tid; i < 2048; i += 256) ws[i] = g_w[i];
    __syncthreads();
    const int r = blockIdx.x * 8 + (tid >> 5);
    const int lane = tid & 31;
    const size_t base = (size_t)r * 256 + lane * 8;
    uint4 a0 = *(const uint4*)(g_x0 + base);
    uint4 a1 = *(const uint4*)(g_x1 + base);
    const __half* h0p = (const __half*)&a0;
    const __half* h1p = (const __half*)&a1;
    float xt[8];
#pragma unroll
    for (int j = 0; j < 8; j++) xt[j] = __half2float(h0p[j]) + __half2float(h1p[j]);
#pragma unroll
    for (int n = 0; n < 8; n++) {
        float p = 0.0f;
#pragma unroll
        for (int j = 0; j < 8; j++) p += xt[j] * ws[n * 256 + lane * 8 + j];
#pragma unroll
        for (int off = 16; off > 0; off >>= 1)
            p += __shfl_xor_sync(0xffffffffu, p, off);
        if (lane == 0) g_s[(size_t)n * 32768 + r] = p + g_cn[n];
    }
}

// ---------------------------------------------------------------------------
// WMMA GEMM (round-15 proven): 256 thr, tile 128x128, warp 32x64 (4x2),
// K-chunk 64, 3-stage cp.async, single sync per tile.
// ---------------------------------------------------------------------------
template <int NT>
__global__ __launch_bounds__(256) void k_mma(
    const __half* __restrict__ A0g, const __half* __restrict__ A1g,
    const __half* __restrict__ B0g, const __half* __restrict__ B1g,
    float* __restrict__ Cf, __half* __restrict__ C0g, __half* __restrict__ C1g,
    const float* __restrict__ bias, long long biasHi, float alpha,
    int Ktot, int lda, int ldb, int ldc, int gather,
    long long aHi, long long bHi, long long cHi)
{
    constexpr int LDA = 72, LDB = 72;
    constexpr int PL  = (NT > 1) ? 2 : 1;
    constexpr int APL = 128 * LDA * 2;
    constexpr int BPL = 128 * LDB * 2;
    constexpr int STAGE = PL * (APL + BPL);

    extern __shared__ __align__(1024) char sm[];

    const int tid = threadIdx.x;
    const int w = tid >> 5;
    const int wm = w & 3;
    const int wn = w >> 2;
    const long long aoff = (long long)blockIdx.z * aHi;
    const long long boff = (long long)blockIdx.z * bHi;
    const long long coff = (long long)blockIdx.z * cHi;
    const float* biasz = bias ? (bias + (long long)blockIdx.z * biasHi) : (const float*)0;
    const int m0 = blockIdx.y * 128;
    const int n0 = blockIdx.x * 128;

    int crow[4], ck[4];
#pragma unroll
    for (int i = 0; i < 4; i++) {
        int id = tid + i * 256;
        crow[i] = id >> 3;
        ck[i] = (id & 7) * 8;
    }

    auto a_row = [&](int r) -> long long {
        int g = m0 + r;
        return gather ? (long long)(((g >> 6) << 8) + (g & 63)) : (long long)g;
    };

    wmma::fragment<wmma::accumulator, 16, 16, 16, float> acc[2][4];
#pragma unroll
    for (int mf = 0; mf < 2; mf++)
#pragma unroll
        for (int nf = 0; nf < 4; nf++) wmma::fill_fragment(acc[mf][nf], 0.0f);

    auto cp_tile = [&](int k0, int buf) {
        char* base = sm + buf * STAGE;
        __half* sA0 = (__half*)base;
        __half* sA1 = (__half*)(base + APL);
        __half* sB0 = (__half*)(base + PL * APL);
        __half* sB1 = (__half*)(base + PL * APL + BPL);
#pragma unroll
        for (int i = 0; i < 4; i++) {
            long long ga = aoff + a_row(crow[i]) * lda + k0 + ck[i];
            cp16(sA0 + crow[i] * LDA + ck[i], A0g + ga);
            if (NT > 1) cp16(sA1 + crow[i] * LDA + ck[i], A1g + ga);
            long long gb = boff + (long long)(n0 + crow[i]) * ldb + k0 + ck[i];
            cp16(sB0 + crow[i] * LDB + ck[i], B0g + gb);
            if (NT > 1) cp16(sB1 + crow[i] * LDB + ck[i], B1g + gb);
        }
        CP_COMMIT();
    };

    auto mma_tile = [&](int buf) {
        const char* base = sm + buf * STAGE;
        const __half* sA0 = (const __half*)(base);
        const __half* sA1 = (const __half*)(base + APL);
        const __half* sB0 = (const __half*)(base + PL * APL);
        const __half* sB1 = (const __half*)(base + PL * APL + BPL);
#pragma unroll
        for (int ks = 0; ks < 64; ks += 16) {
            wmma::fragment<wmma::matrix_a, 16, 16, 16, __half, wmma::row_major> a0f[2], a1f[2];
#pragma unroll
            for (int mf = 0; mf < 2; mf++) {
                int r0 = wm * 32 + mf * 16;
                wmma::load_matrix_sync(a0f[mf], sA0 + r0 * LDA + ks, LDA);
                if (NT > 1) wmma::load_matrix_sync(a1f[mf], sA1 + r0 * LDA + ks, LDA);
            }
#pragma unroll
            for (int nf = 0; nf < 4; nf++) {
                int col = wn * 64 + nf * 16;
                wmma::fragment<wmma::matrix_b, 16, 16, 16, __half, wmma::col_major> b0f, b1f;
                wmma::load_matrix_sync(b0f, sB0 + col * LDB + ks, LDB);
                if (NT > 1) wmma::load_matrix_sync(b1f, sB1 + col * LDB + ks, LDB);
#pragma unroll
                for (int mf = 0; mf < 2; mf++) {
                    wmma::mma_sync(acc[mf][nf], a0f[mf], b0f, acc[mf][nf]);
                    if (NT > 1) {
                        wmma::mma_sync(acc[mf][nf], a0f[mf], b1f, acc[mf][nf]);
                        wmma::mma_sync(acc[mf][nf], a1f[mf], b0f, acc[mf][nf]);
                    }
                }
            }
        }
    };

    const int numK = Ktot >> 6;
    cp_tile(0, 0);
    if (numK > 1) cp_tile(64, 1);
    for (int t = 0; t < numK; t++) {
        if (t + 1 < numK) cp_wait1(); else cp_wait0();
        __syncthreads();
        if (t + 2 < numK) cp_tile((t + 2) << 6, (t + 2) % 3);
        mma_tile(t % 3);
    }
    __syncthreads();

    float* Csm = (float*)sm;
#pragma unroll
    for (int mf = 0; mf < 2; mf++)
#pragma unroll
        for (int nf = 0; nf < 4; nf++) {
            int r0 = wm * 32 + mf * 16, c0 = wn * 64 + nf * 16;
            wmma::store_matrix_sync(Csm + r0 * 128 + c0, acc[mf][nf], 128, wmma::mem_row_major);
        }
    __syncthreads();

#pragma unroll
    for (int i = 0; i < 16; i++) {
        int f = tid + i * 256;
        int row = f >> 5, c4 = (f & 31) * 4;
        float4 v = *(float4*)(Csm + row * 128 + c4);
        v.x *= alpha; v.y *= alpha; v.z *= alpha; v.w *= alpha;
        if (biasz) {
            v.x += biasz[n0 + c4 + 0]; v.y += biasz[n0 + c4 + 1];
            v.z += biasz[n0 + c4 + 2]; v.w += biasz[n0 + c4 + 3];
        }
        long long o = coff + (long long)(m0 + row) * ldc + n0 + c4;
        if (Cf) {
            *(float4*)(Cf + o) = v;
        } else {
            __half x0, x1, y0, y1, z0, z1, w0, w1;
            split2(v.x, x0, x1); split2(v.y, y0, y1);
            split2(v.z, z0, z1); split2(v.w, w0, w1);
            __half2 p0 = __halves2half2(x0, y0), q0 = __halves2half2(z0, w0);
            *(uint2*)(C0g + o) = make_uint2(h2u(p0), h2u(q0));
            if (C1g) {
                __half2 p1 = __halves2half2(x1, y1), q1 = __halves2half2(z1, w1);
                *(uint2*)(C1g + o) = make_uint2(h2u(p1), h2u(q1));
            }
        }
    }
}

// ---------------------------------------------------------------------------
// Fused attention per (b, n) CTA:
//  P0: T[64,256] = x~a @ F_n   (K=256, 3-term, 2-stage cp.async)
//  T -> fp32 smem -> split2 -> Tsm planes
//  P1: S[64,256] = T @ x~_b^T  (K=256, 3-term; A resident in smem)
//  S += s[n, b*256+e] -> softmax -> P fp16
//  P3: U[64,512] = P @ h_b     (1-term, 3-stage)
// smem 215040:
//  P0 stage 2x92160 @0 | Ssm 67584 @0 | Tsm planes @147456 (2x33792)
//  P1 stage 2x73728 @0 | Ssm @0 | Psm @67584 (33792) | P3 3x16896 @0 | Csm @0
// ---------------------------------------------------------------------------
#define ATTN_SMEM 215040
#define P0_STAGE 92160
#define P0_APL 9216
#define P0_BOFF 18432
#define P0_BPL 36864
#define TSM0_OFF 147456
#define TSM1_OFF 181248
#define P1_STAGE 73728

__global__ __launch_bounds__(256) void k_attn() {
    extern __shared__ __align__(1024) char sm[];
    const int tid = threadIdx.x;
    const int w = tid >> 5, lane = tid & 31;
    const int wm = w & 1, wn = w >> 1;     // 2x4 warps, warp tile 32x64
    const int b = blockIdx.x, n = blockIdx.y;

    float* Ssm = (float*)sm;
    __half* Psm0 = (__half*)(sm + 67584);
    __half* Tsm0 = (__half*)(sm + TSM0_OFF);
    __half* Tsm1 = (__half*)(sm + TSM1_OFF);

    const __half* Xb0 = g_x0 + (size_t)b * 256 * 256;   // [256 rows, 256 k]
    const __half* Xb1 = g_x1 + (size_t)b * 256 * 256;
    const __half* F0 = g_TF0 + (size_t)n * 65536;       // F^T [256 j, 256 i]
    const __half* F1 = g_TF1 + (size_t)n * 65536;
    const __half* Hb0 = g_h0 + (size_t)b * 256 * 512;

    wmma::fragment<wmma::accumulator, 16, 16, 16, float> acc[2][4];
#pragma unroll
    for (int mf = 0; mf < 2; mf++)
#pragma unroll
        for (int nf = 0; nf < 4; nf++) wmma::fill_fragment(acc[mf][nf], 0.0f);

    // ======== P0: T = x~a @ F_n  (K=256, 4 chunks of 64, 3-term) =========
    {
        auto p0_cp = [&](int k0, int buf) {
            char* base = sm + buf * P0_STAGE;
            __half* sA0 = (__half*)base;
            __half* sA1 = (__half*)(base + P0_APL);
            __half* sB0 = (__half*)(base + P0_BOFF);
            __half* sB1 = (__half*)(base + P0_BOFF + P0_BPL);
#pragma unroll
            for (int i = 0; i < 2; i++) {
                int id = tid + i * 256;
                int ar = id >> 3, akc = (id & 7) * 8;
                long long ga = (long long)ar * 256 + k0 + akc;   // lda = 256
                cp16(sA0 + ar * 72 + akc, Xb0 + ga);
                cp16(sA1 + ar * 72 + akc, Xb1 + ga);
            }
#pragma unroll
            for (int i = 0; i < 8; i++) {
                int id = tid + i * 256;
                int br = id >> 3, bkc = (id & 7) * 8;
                long long gb = (long long)br * 256 + k0 + bkc;   // ldb = 256
                cp16(sB0 + br * 72 + bkc, F0 + gb);
                cp16(sB1 + br * 72 + bkc, F1 + gb);
            }
            CP_COMMIT();
        };
        auto p0_mma = [&](int buf) {
            const char* base = sm + buf * P0_STAGE;
            const __half* sA0 = (const __half*)base;
            const __half* sA1 = (const __half*)(base + P0_APL);
            const __half* sB0 = (const __half*)(base + P0_BOFF);
            const __half* sB1 = (const __half*)(base + P0_BOFF + P0_BPL);
#pragma unroll
            for (int ks = 0; ks < 64; ks += 16) {
                wmma::fragment<wmma::matrix_a, 16, 16, 16, __half, wmma::row_major> a0f[2], a1f[2];
#pragma unroll
                for (int mf = 0; mf < 2; mf++) {
                    int r0 = wm * 32 + mf * 16;
                    wmma::load_matrix_sync(a0f[mf], sA0 + r0 * 72 + ks, 72);
                    wmma::load_matrix_sync(a1f[mf], sA1 + r0 * 72 + ks, 72);
                }
#pragma unroll
                for (int nf = 0; nf < 4; nf++) {
                    int col = wn * 64 + nf * 16;
                    wmma::fragment<wmma::matrix_b, 16, 16, 16, __half, wmma::col_major> b0f, b1f;
                    wmma::load_matrix_sync(b0f, sB0 + col * 72 + ks, 72);
                    wmma::load_matrix_sync(b1f, sB1 + col * 72 + ks, 72);
#pragma unroll
                    for (int mf = 0; mf < 2; mf++) {
                        wmma::mma_sync(acc[mf][nf], a0f[mf], b0f, acc[mf][nf]);
                        wmma::mma_sync(acc[mf][nf], a0f[mf], b1f, acc[mf][nf]);
                        wmma::mma_sync(acc[mf][nf], a1f[mf], b0f, acc[mf][nf]);
                    }
                }
            }
        };
        p0_cp(0, 0);
        for (int t = 0; t < 4; t++) {
            cp_wait0();
            __syncthreads();
            if (t + 1 < 4) p0_cp((t + 1) << 6, (t + 1) & 1);
            p0_mma(t & 1);
        }
        __syncthreads();
    }

    // ---- stage T fp32 -> split to Tsm planes
#pragma unroll
    for (int mf = 0; mf < 2; mf++)
#pragma unroll
        for (int nf = 0; nf < 4; nf++) {
            int r0 = wm * 32 + mf * 16, c0 = wn * 64 + nf * 16;
            wmma::store_matrix_sync(Ssm + r0 * 264 + c0, acc[mf][nf], 264, wmma::mem_row_major);
        }
    __syncthreads();
#pragma unroll
    for (int i = 0; i < 16; i++) {
        int id = tid + i * 256;
        int row = id >> 6, c4 = (id & 63) * 4;
        float4 v = *(float4*)(Ssm + row * 264 + c4);
        __half x0, x1, y0, y1, z0, z1, w0, w1;
        split2(v.x, x0, x1); split2(v.y, y0, y1);
        split2(v.z, z0, z1); split2(v.w, w0, w1);
        __half2 p0 = __halves2half2(x0, y0), q0 = __halves2half2(z0, w0);
        __half2 p1 = __halves2half2(x1, y1), q1 = __halves2half2(z1, w1);
        *(uint2*)(Tsm0 + row * 264 + c4) = make_uint2(h2u(p0), h2u(q0));
        *(uint2*)(Tsm1 + row * 264 + c4) = make_uint2(h2u(p1), h2u(q1));
    }
    __syncthreads();

    // ======== P1: S = T @ x~_b^T  (K=256, 4 chunks; A resident) ==========
#pragma unroll
    for (int mf = 0; mf < 2; mf++)
#pragma unroll
        for (int nf = 0; nf < 4; nf++) wmma::fill_fragment(acc[mf][nf], 0.0f);
    {
        auto p1_cp = [&](int k0, int buf) {
            char* base = sm + buf * P1_STAGE;
            __half* sB0 = (__half*)base;
            __half* sB1 = (__half*)(base + P0_BPL);
#pragma unroll
            for (int i = 0; i < 8; i++) {
                int id = tid + i * 256;
                int br = id >> 3, bkc = (id & 7) * 8;
                long long gb = (long long)br * 256 + k0 + bkc;
                cp16(sB0 + br * 72 + bkc, Xb0 + gb);
                cp16(sB1 + br * 72 + bkc, Xb1 + gb);
            }
            CP_COMMIT();
        };
        auto p1_mma = [&](int buf, int t) {
            const char* base = sm + buf * P1_STAGE;
            const __half* sB0 = (const __half*)base;
            const __half* sB1 = (const __half*)(base + P0_BPL);
#pragma unroll
            for (int ks = 0; ks < 64; ks += 16) {
                wmma::fragment<wmma::matrix_a, 16, 16, 16, __half, wmma::row_major> a0f[2], a1f[2];
#pragma unroll
                for (int mf = 0; mf < 2; mf++) {
                    int r0 = wm * 32 + mf * 16;
                    wmma::load_matrix_sync(a0f[mf], Tsm0 + r0 * 264 + t * 64 + ks, 264);
                    wmma::load_matrix_sync(a1f[mf], Tsm1 + r0 * 264 + t * 64 + ks, 264);
                }
#pragma unroll
                for (int nf = 0; nf < 4; nf++) {
                    int col = wn * 64 + nf * 16;
                    wmma::fragment<wmma::matrix_b, 16, 16, 16, __half, wmma::col_major> b0f, b1f;
                    wmma::load_matrix_sync(b0f, sB0 + col * 72 + ks, 72);
                    wmma::load_matrix_sync(b1f, sB1 + col * 72 + ks, 72);
#pragma unroll
                    for (int mf = 0; mf < 2; mf++) {
                        wmma::mma_sync(acc[mf][nf], a0f[mf], b0f, acc[mf][nf]);
                        wmma::mma_sync(acc[mf][nf], a0f[mf], b1f, acc[mf][nf]);
                        wmma::mma_sync(acc[mf][nf], a1f[mf], b0f, acc[mf][nf]);
                    }
                }
            }
        };
        p1_cp(0, 0);
        for (int t = 0; t < 4; t++) {
            cp_wait0();
            __syncthreads();
            if (t + 1 < 4) p1_cp((t + 1) << 6, (t + 1) & 1);
            p1_mma(t & 1, t);
        }
        __syncthreads();
    }

    // ---- stage S fp32
#pragma unroll
    for (int mf = 0; mf < 2; mf++)
#pragma unroll
        for (int nf = 0; nf < 4; nf++) {
            int r0 = wm * 32 + mf * 16, c0 = wn * 64 + nf * 16;
            wmma::store_matrix_sync(Ssm + r0 * 264 + c0, acc[mf][nf], 264, wmma::mem_row_major);
        }
    __syncthreads();

    // ======== softmax (+ s column term) ========
    const float* svp = g_s + (size_t)n * 32768 + (size_t)b * 256 + lane * 8;
    float4 sv0 = *(const float4*)svp;
    float4 sv1 = *(const float4*)(svp + 4);
#pragma unroll
    for (int i = 0; i < 8; i++) {
        int r = w * 8 + i;
        float* srow = Ssm + (size_t)r * 264 + lane * 8;
        float4 v0 = *(float4*)srow;
        float4 v1 = *(float4*)(srow + 4);
        v0.x += sv0.x; v0.y += sv0.y; v0.z += sv0.z; v0.w += sv0.w;
        v1.x += sv1.x; v1.y += sv1.y; v1.z += sv1.z; v1.w += sv1.w;
        float m = fmaxf(fmaxf(fmaxf(v0.x, v0.y), fmaxf(v0.z, v0.w)),
                        fmaxf(fmaxf(v1.x, v1.y), fmaxf(v1.z, v1.w)));
#pragma unroll
        for (int off = 16; off > 0; off >>= 1)
            m = fmaxf(m, __shfl_xor_sync(0xffffffffu, m, off));
        v0.x = __expf(v0.x - m); v0.y = __expf(v0.y - m);
        v0.z = __expf(v0.z - m); v0.w = __expf(v0.w - m);
        v1.x = __expf(v1.x - m); v1.y = __expf(v1.y - m);
        v1.z = __expf(v1.z - m); v1.w = __expf(v1.w - m);
        float s = v0.x + v0.y + v0.z + v0.w + v1.x + v1.y + v1.z + v1.w;
#pragma unroll
        for (int off = 16; off > 0; off >>= 1)
            s += __shfl_xor_sync(0xffffffffu, s, off);
        const float inv = 1.0f / s;
        __align__(16) __half h0[8];
        h0[0] = __float2half_rn(v0.x * inv); h0[1] = __float2half_rn(v0.y * inv);
        h0[2] = __float2half_rn(v0.z * inv); h0[3] = __float2half_rn(v0.w * inv);
        h0[4] = __float2half_rn(v1.x * inv); h0[5] = __float2half_rn(v1.y * inv);
        h0[6] = __float2half_rn(v1.z * inv); h0[7] = __float2half_rn(v1.w * inv);
        *(uint4*)(Psm0 + (size_t)r * 264 + lane * 8) = *(uint4*)h0;
    }
    __syncthreads();

    // ======== P3: U = P @ h  (1-term; two halves; K=256; 3-stage) =========
    for (int hh = 0; hh < 2; hh++) {
        const int d0 = hh * 256;
#pragma unroll
        for (int mf = 0; mf < 2; mf++)
#pragma unroll
            for (int nf = 0; nf < 4; nf++) wmma::fill_fragment(acc[mf][nf], 0.0f);

        auto p3_cp = [&](int k0, int buf) {
            __half* sH0 = (__half*)(sm + buf * 16896);
#pragma unroll
            for (int i = 0; i < 4; i++) {
                int id = tid + i * 256;
                int er = id >> 5, dc = (id & 31) * 8;
                cp16(sH0 + er * 264 + dc, Hb0 + (size_t)(k0 + er) * 512 + d0 + dc);
            }
            CP_COMMIT();
        };
        auto p3_mma = [&](int buf, int c) {
            const __half* sH0 = (const __half*)(sm + buf * 16896);
#pragma unroll
            for (int ks = 0; ks < 32; ks += 16) {
                wmma::fragment<wmma::matrix_a, 16, 16, 16, __half, wmma::row_major> a0f[2];
#pragma unroll
                for (int mf = 0; mf < 2; mf++) {
                    int r0 = wm * 32 + mf * 16;
                    wmma::load_matrix_sync(a0f[mf], Psm0 + r0 * 264 + c * 32 + ks, 264);
                }
#pragma unroll
                for (int nf = 0; nf < 4; nf++) {
                    int col = wn * 64 + nf * 16;
                    wmma::fragment<wmma::matrix_b, 16, 16, 16, __half, wmma::row_major> b0f;
                    wmma::load_matrix_sync(b0f, sH0 + ks * 264 + col, 264);
#pragma unroll
                    for (int mf = 0; mf < 2; mf++)
                        wmma::mma_sync(acc[mf][nf], a0f[mf], b0f, acc[mf][nf]);
                }
            }
        };
        p3_cp(0, 0);
        p3_cp(32, 1);
        for (int c = 0; c < 8; c++) {
            if (c + 1 < 8) cp_wait1(); else cp_wait0();
            __syncthreads();
            if (c + 2 < 8) p3_cp((c + 2) << 5, (c + 2) % 3);
            p3_mma(c % 3, c);
        }
        __syncthreads();

        float* Csm = (float*)sm;
#pragma unroll
        for (int mf = 0; mf < 2; mf++)
#pragma unroll
            for (int nf = 0; nf < 4; nf++) {
                int r0 = wm * 32 + mf * 16, c0 = wn * 64 + nf * 16;
                wmma::store_matrix_sync(Csm + r0 * 264 + c0, acc[mf][nf], 264, wmma::mem_row_major);
            }
        __syncthreads();
#pragma unroll
        for (int i = 0; i < 16; i++) {
            int id = tid + i * 256;
            int row = id >> 6, c4 = (id & 63) * 4;
            float4 v = *(float4*)(Csm + row * 264 + c4);
            __align__(8) __half h4[4];
            h4[0] = __float2half_rn(v.x); h4[1] = __float2half_rn(v.y);
            h4[2] = __float2half_rn(v.z); h4[3] = __float2half_rn(v.w);
            size_t o = (((size_t)(b * 64 + row)) * 8 + n) * 512 + d0 + c4;
            *(uint2*)(g_U0 + o) = *(uint2*)h4;
        }
        __syncthreads();
    }
}

// ---------------------------------------------------------------------------
extern "C" void kernel_launch(void* const* d_in, const int* in_sizes, int n_in,
                              void* d_out, int out_size) {
    const float* x     = (const float*)d_in[0];
    const float* W_enc = (const float*)d_in[1];
    const float* b_enc = (const float*)d_in[2];
    const float* WQ    = (const float*)d_in[3];
    const float* WK    = (const float*)d_in[4];
    const float* WV    = (const float*)d_in[5];
    float* out = (float*)d_out;

    const int SM3 = 3 * 2 * (128 * 72 * 2 + 128 * 72 * 2);   // 221184
    const int SM1 = 3 * (128 * 72 * 2 + 128 * 72 * 2);       // 110592
    cudaFuncSetAttribute(k_mma<3>, cudaFuncAttributeMaxDynamicSharedMemorySize, SM3);
    cudaFuncSetAttribute(k_mma<1>, cudaFuncAttributeMaxDynamicSharedMemorySize, SM1);
    cudaFuncSetAttribute(k_attn, cudaFuncAttributeMaxDynamicSharedMemorySize, ATTN_SMEM);

    void *p_M, *p_E, *p_F, *p_x0, *p_x1, *p_h0, *p_U0;
    void *p_e0, *p_e1, *p_we0, *p_we1, *p_m0, *p_m1, *p_E0, *p_E1, *p_F0, *p_F1;
    void *p_w0, *p_w1, *p_k0, *p_k1, *p_q0, *p_q1;
    cudaGetSymbolAddress(&p_M, g_M);
    cudaGetSymbolAddress(&p_E, g_E);
    cudaGetSymbolAddress(&p_F, g_F);
    cudaGetSymbolAddress(&p_x0, g_x0); cudaGetSymbolAddress(&p_x1, g_x1);
    cudaGetSymbolAddress(&p_h0, g_h0);
    cudaGetSymbolAddress(&p_U0, g_U0);
    cudaGetSymbolAddress(&p_e0, g_Te0); cudaGetSymbolAddress(&p_e1, g_Te1);
    cudaGetSymbolAddress(&p_we0, g_We0); cudaGetSymbolAddress(&p_we1, g_We1);
    cudaGetSymbolAddress(&p_m0, g_Tm0); cudaGetSymbolAddress(&p_m1, g_Tm1);
    cudaGetSymbolAddress(&p_E0, g_TE0); cudaGetSymbolAddress(&p_E1, g_TE1);
    cudaGetSymbolAddress(&p_F0, g_TF0); cudaGetSymbolAddress(&p_F1, g_TF1);
    cudaGetSymbolAddress(&p_w0, g_Tw0); cudaGetSymbolAddress(&p_w1, g_Tw1);
    cudaGetSymbolAddress(&p_k0, g_Wk0); cudaGetSymbolAddress(&p_k1, g_Wk1);
    cudaGetSymbolAddress(&p_q0, g_Wq0); cudaGetSymbolAddress(&p_q1, g_Wq1);

    // 0: x split
    k_xsplit<<<dim3(2048), 256>>>(x, (__half*)p_x0, (__half*)p_x1, (size_t)32768 * 256 / 4);
    // 1: We + WK + WQ elementwise splits
    k_split3<<<dim3(512), 256>>>(
        W_enc, (__half*)p_we0, (__half*)p_we1, (size_t)256 * 512,
        WK, (__half*)p_k0, (__half*)p_k1, (size_t)8 * 512 * 512,
        WQ, (__half*)p_q0, (__half*)p_q1, (size_t)8 * 512 * 512);
    // 2: W_enc^T split
    k_tsplit2<<<dim3(8, 16, 1), dim3(32, 8)>>>(W_enc, (__half*)p_e0, (__half*)p_e1, 256, 512);
    // 3: encode (PROFILE TARGET): h = xp @ Te + b  (single fp16 plane out)
    k_mma<3><<<dim3(4, 256, 1), 256, SM3>>>(
        (const __half*)p_x0, (const __half*)p_x1,
        (const __half*)p_e0, (const __half*)p_e1,
        nullptr, (__half*)p_h0, nullptr, b_enc, 0, 1.0f,
        256, 256, 256, 512, 0, 0, 0, 0);
    // 4: WV^T split
    k_tsplit2<<<dim3(128, 16, 1), dim3(32, 8)>>>(WV, (__half*)p_w0, (__half*)p_w1, 4096, 512);
    // 5: M_n = (WQ_n @ WK_n^T) * scale
    k_mma<3><<<dim3(4, 4, 8), 256, SM3>>>(
        (const __half*)p_q0, (const __half*)p_q1,
        (const __half*)p_k0, (const __half*)p_k1,
        (float*)p_M, nullptr, nullptr, nullptr, 0, 0.04419417382415922f,
        512, 512, 512, 512, 0,
        (long long)512 * 512, (long long)512 * 512, (long long)512 * 512);
    // 6: M^T split
    k_tsplit2<<<dim3(16, 16, 8), dim3(32, 8)>>>((const float*)p_M, (__half*)p_m0, (__half*)p_m1, 512, 512);
    // 7: bv = b @ M
    k_bv<<<dim3(8), 512>>>(b_enc);
    // 8: w = We @ bv, cn = bv.b
    k_wv<<<dim3(8), 256>>>(W_enc, b_enc);
    // 9: s[n,r] = w_n . x~_r + cn
    k_sv<<<dim3(4096), 256>>>();
    // 10: E_n = W_enc @ M_n
    k_mma<3><<<dim3(4, 2, 8), 256, SM3>>>(
        (const __half*)p_we0, (const __half*)p_we1,
        (const __half*)p_m0, (const __half*)p_m1,
        (float*)p_E, nullptr, nullptr, nullptr, 0, 1.0f,
        512, 512, 512, 512, 0,
        0, (long long)512 * 512, (long long)256 * 512);
    // 11: E elementwise split (row-major planes)
    k_split2e<<<dim3(512), 256>>>((const float*)p_E, (__half*)p_E0, (__half*)p_E1,
                                  (size_t)8 * 256 * 512);
    // 12: F_n = E_n @ W_enc^T  (B = We row planes)
    k_mma<3><<<dim3(2, 2, 8), 256, SM3>>>(
        (const __half*)p_E0, (const __half*)p_E1,
        (const __half*)p_we0, (const __half*)p_we1,
        (float*)p_F, nullptr, nullptr, nullptr, 0, 1.0f,
        512, 512, 512, 256, 0,
        (long long)256 * 512, 0, (long long)256 * 256);
    // 13: F^T split -> TF planes
    k_tsplit2<<<dim3(8, 8, 8), dim3(32, 8)>>>((const float*)p_F, (__half*)p_F0, (__half*)p_F1, 256, 256);
    // 14: fused attention
    k_attn<<<dim3(128, 8), 256, ATTN_SMEM>>>();
    // 15: out = (1/8) U @ WVcat  (1-term)
    k_mma<1><<<dim3(4, 64, 1), 256, SM1>>>(
        (const __half*)p_U0, nullptr,
        (const __half*)p_w0, nullptr,
        out, nullptr, nullptr, nullptr, 0, 0.125f,
        4096, 4096, 4096, 512, 0, 0, 0, 0);
}